// round 1
// baseline (speedup 1.0000x reference)
#include <cuda_runtime.h>
#include <math.h>

// Problem constants
constexpr int Bc = 8;
constexpr int Cc = 64;
constexpr int Nc = 4096;
constexpr int Kc = 20;
constexpr int Oc = 64;
constexpr float BN_EPS = 1e-5f;
constexpr float NEG_SLOPE = 0.2f;
constexpr float FLT_BIG = 3.4e38f;

// -------------------- device scratch (no allocations allowed) --------------------
__device__ float  g_xx[Bc * Nc];            // squared norms
__device__ int    g_idx[Bc * Nc * Kc];      // knn indices
__device__ float  g_P[Bc * Nc * Oc];        // W1 . x_j   projection
__device__ float  g_Q[Bc * Nc * Oc];        // (W2-W1) . x_i projection
__device__ float  g_mx[Bc * Nc * Oc];       // max_k h
__device__ float  g_mn[Bc * Nc * Oc];       // min_k h
__device__ double g_sum[Oc];
__device__ double g_sumsq[Oc];
__device__ float  g_scale[Oc];
__device__ float  g_shift[Oc];
__device__ float  g_W1t[Cc * Oc];           // W[:, :C]   transposed [c][o]
__device__ float  g_Wdt[Cc * Oc];           // W[:, C:] - W[:, :C] transposed [c][o]

// -------------------- kernel: squared norms --------------------
__global__ void k_xx(const float* __restrict__ x) {
    int t = blockIdx.x * blockDim.x + threadIdx.x;    // over B*N
    int b = t >> 12;          // /N
    int n = t & (Nc - 1);
    const float* xb = x + (size_t)b * Cc * Nc + n;
    float s = 0.f;
#pragma unroll
    for (int c = 0; c < Cc; ++c) {
        float v = xb[c * Nc];
        s = fmaf(v, v, s);
    }
    g_xx[t] = s;
}

// -------------------- kernel: prep W transposes + zero stats --------------------
__global__ void k_prep(const float* __restrict__ W) {
    int t = blockIdx.x * blockDim.x + threadIdx.x;
    if (t < Cc * Oc) {
        int c = t & 63;
        int o = t >> 6;
        float w1 = W[o * (2 * Cc) + c];
        float w2 = W[o * (2 * Cc) + Cc + c];
        g_W1t[c * Oc + o] = w1;
        g_Wdt[c * Oc + o] = w2 - w1;
    }
    if (blockIdx.x == 0 && t < Oc) {
        g_sum[t] = 0.0;
        g_sumsq[t] = 0.0;
    }
}

// -------------------- kernel: P and Q projections --------------------
// P[b,n,o] = sum_c W1[o,c]   * x[b,c,n]
// Q[b,n,o] = sum_c Wd[o,c]   * x[b,c,n]
__global__ void __launch_bounds__(256) k_pq(const float* __restrict__ x) {
    int b  = blockIdx.y;
    int n0 = blockIdx.x * 32;
    int o  = threadIdx.x & 63;
    int gg = threadIdx.x >> 6;   // 0..3, each group handles 8 n
    __shared__ float xs[Cc][36]; // [c][nn], padded (36 % 4 == 0)

    for (int t = threadIdx.x; t < Cc * 32; t += 256) {
        int nn = t & 31;
        int c  = t >> 5;
        xs[c][nn] = x[(size_t)b * Cc * Nc + c * Nc + n0 + nn];
    }
    __syncthreads();

    float ap[8], aq[8];
#pragma unroll
    for (int r = 0; r < 8; ++r) { ap[r] = 0.f; aq[r] = 0.f; }
    const int nbase = gg * 8;

#pragma unroll 8
    for (int c = 0; c < Cc; ++c) {
        float w1 = __ldg(&g_W1t[c * Oc + o]);
        float wd = __ldg(&g_Wdt[c * Oc + o]);
        float4 v0 = *(const float4*)&xs[c][nbase];
        float4 v1 = *(const float4*)&xs[c][nbase + 4];
        ap[0] = fmaf(w1, v0.x, ap[0]); aq[0] = fmaf(wd, v0.x, aq[0]);
        ap[1] = fmaf(w1, v0.y, ap[1]); aq[1] = fmaf(wd, v0.y, aq[1]);
        ap[2] = fmaf(w1, v0.z, ap[2]); aq[2] = fmaf(wd, v0.z, aq[2]);
        ap[3] = fmaf(w1, v0.w, ap[3]); aq[3] = fmaf(wd, v0.w, aq[3]);
        ap[4] = fmaf(w1, v1.x, ap[4]); aq[4] = fmaf(wd, v1.x, aq[4]);
        ap[5] = fmaf(w1, v1.y, ap[5]); aq[5] = fmaf(wd, v1.y, aq[5]);
        ap[6] = fmaf(w1, v1.z, ap[6]); aq[6] = fmaf(wd, v1.z, aq[6]);
        ap[7] = fmaf(w1, v1.w, ap[7]); aq[7] = fmaf(wd, v1.w, aq[7]);
    }

    int row0 = b * Nc + n0 + nbase;
#pragma unroll
    for (int r = 0; r < 8; ++r) {
        g_P[(size_t)(row0 + r) * Oc + o] = ap[r];
        g_Q[(size_t)(row0 + r) * Oc + o] = aq[r];
    }
}

// -------------------- kernel: brute-force KNN (top-K smallest distances) --------------------
// One thread per query point. 64 threads/block -> 512 blocks.
constexpr int TJ = 64;
__global__ void __launch_bounds__(64) k_knn(const float* __restrict__ x) {
    int b = blockIdx.y;
    int i = blockIdx.x * 64 + threadIdx.x;
    const float* xb = x + (size_t)b * Cc * Nc;

    float q[Cc];
#pragma unroll
    for (int c = 0; c < Cc; ++c) q[c] = xb[c * Nc + i];
    float xxi = g_xx[b * Nc + i];

    float topd[Kc];
    int   topi[Kc];
#pragma unroll
    for (int kk = 0; kk < Kc; ++kk) { topd[kk] = FLT_BIG; topi[kk] = -1; }
    float worst = FLT_BIG;

    __shared__ float s[TJ][68];  // [jj][c], pad 68 (mult of 4, breaks stride-64 conflicts)
    __shared__ float sxx[TJ];

    for (int j0 = 0; j0 < Nc; j0 += TJ) {
        __syncthreads();
#pragma unroll 8
        for (int t = threadIdx.x; t < TJ * Cc; t += 64) {
            int jj = t & 63;
            int c  = t >> 6;
            s[jj][c] = xb[c * Nc + j0 + jj];
        }
        sxx[threadIdx.x] = g_xx[b * Nc + j0 + threadIdx.x];
        __syncthreads();

#pragma unroll 1
        for (int jj = 0; jj < TJ; jj += 4) {
            float a0 = 0.f, a1 = 0.f, a2 = 0.f, a3 = 0.f;
#pragma unroll
            for (int c = 0; c < Cc; c += 4) {
                float4 v0 = *(const float4*)&s[jj + 0][c];
                float4 v1 = *(const float4*)&s[jj + 1][c];
                float4 v2 = *(const float4*)&s[jj + 2][c];
                float4 v3 = *(const float4*)&s[jj + 3][c];
                a0 = fmaf(q[c], v0.x, a0); a0 = fmaf(q[c+1], v0.y, a0);
                a0 = fmaf(q[c+2], v0.z, a0); a0 = fmaf(q[c+3], v0.w, a0);
                a1 = fmaf(q[c], v1.x, a1); a1 = fmaf(q[c+1], v1.y, a1);
                a1 = fmaf(q[c+2], v1.z, a1); a1 = fmaf(q[c+3], v1.w, a1);
                a2 = fmaf(q[c], v2.x, a2); a2 = fmaf(q[c+1], v2.y, a2);
                a2 = fmaf(q[c+2], v2.z, a2); a2 = fmaf(q[c+3], v2.w, a2);
                a3 = fmaf(q[c], v3.x, a3); a3 = fmaf(q[c+1], v3.y, a3);
                a3 = fmaf(q[c+2], v3.z, a3); a3 = fmaf(q[c+3], v3.w, a3);
            }
            float dv[4];
            dv[0] = xxi + sxx[jj + 0] - 2.f * a0;
            dv[1] = xxi + sxx[jj + 1] - 2.f * a1;
            dv[2] = xxi + sxx[jj + 2] - 2.f * a2;
            dv[3] = xxi + sxx[jj + 3] - 2.f * a3;
#pragma unroll
            for (int r = 0; r < 4; ++r) {
                float d = dv[r];
                if (d < worst) {
                    int jidx = j0 + jj + r;
                    int p = Kc - 1;
                    while (p > 0 && topd[p - 1] > d) {
                        topd[p] = topd[p - 1];
                        topi[p] = topi[p - 1];
                        --p;
                    }
                    topd[p] = d;
                    topi[p] = jidx;
                    worst = topd[Kc - 1];
                }
            }
        }
    }

    int* op = &g_idx[(size_t)(b * Nc + i) * Kc];
#pragma unroll
    for (int kk = 0; kk < Kc; ++kk) op[kk] = topi[kk];
}

// -------------------- kernel: gather + max/min + BN stats --------------------
__global__ void __launch_bounds__(256) k_edge() {
    int o  = threadIdx.x & 63;
    int gg = threadIdx.x >> 6;  // 4 teams of 64 threads
    float s1 = 0.f, s2 = 0.f;

    for (int row = blockIdx.x * 4 + gg; row < Bc * Nc; row += gridDim.x * 4) {
        int b  = row >> 12;
        int nb = b << 12;       // b*N
        float qv = g_Q[(size_t)row * Oc + o];
        const int* ip = &g_idx[(size_t)row * Kc];
        float mx = -FLT_BIG, mn = FLT_BIG;
#pragma unroll
        for (int kk = 0; kk < Kc; ++kk) {
            int j = __ldg(&ip[kk]);
            float h = g_P[(size_t)(nb + j) * Oc + o] + qv;
            mx = fmaxf(mx, h);
            mn = fminf(mn, h);
            s1 += h;
            s2 = fmaf(h, h, s2);
        }
        g_mx[(size_t)row * Oc + o] = mx;
        g_mn[(size_t)row * Oc + o] = mn;
    }

    __shared__ float sa[4][64], sb[4][64];
    sa[gg][o] = s1;
    sb[gg][o] = s2;
    __syncthreads();
    if (gg == 0) {
        float t1 = sa[0][o] + sa[1][o] + sa[2][o] + sa[3][o];
        float t2 = sb[0][o] + sb[1][o] + sb[2][o] + sb[3][o];
        atomicAdd(&g_sum[o], (double)t1);
        atomicAdd(&g_sumsq[o], (double)t2);
    }
}

// -------------------- kernel: finalize BN affine --------------------
__global__ void k_fin(const float* __restrict__ gamma, const float* __restrict__ beta) {
    int o = threadIdx.x;
    const double cnt = (double)Bc * Nc * Kc;
    double mean = g_sum[o] / cnt;
    double var  = g_sumsq[o] / cnt - mean * mean;
    float a = gamma[o] * rsqrtf((float)var + BN_EPS);
    g_scale[o] = a;
    g_shift[o] = beta[o] - (float)mean * a;
}

// -------------------- kernel: apply affine + leaky + transpose to [B,O,N] --------------------
__global__ void __launch_bounds__(256) k_out(float* __restrict__ out) {
    int b  = blockIdx.y;
    int n0 = blockIdx.x * 64;
    __shared__ float sh[64][65];

    for (int t = threadIdx.x; t < 4096; t += 256) {
        int o  = t & 63;
        int nn = t >> 6;
        int row = b * Nc + n0 + nn;
        float a = g_scale[o];
        float m = (a >= 0.f) ? g_mx[(size_t)row * Oc + o] : g_mn[(size_t)row * Oc + o];
        float v = fmaf(a, m, g_shift[o]);
        v = (v >= 0.f) ? v : NEG_SLOPE * v;
        sh[o][nn] = v;
    }
    __syncthreads();
    for (int t = threadIdx.x; t < 4096; t += 256) {
        int nn = t & 63;
        int o  = t >> 6;
        out[((size_t)(b * Oc + o)) * Nc + n0 + nn] = sh[o][nn];
    }
}

// -------------------- launch --------------------
extern "C" void kernel_launch(void* const* d_in, const int* in_sizes, int n_in,
                              void* d_out, int out_size) {
    const float* x     = (const float*)d_in[0];   // [B, C, N]
    const float* W     = (const float*)d_in[1];   // [O, 2C]
    const float* gamma = (const float*)d_in[2];   // [O]
    const float* beta  = (const float*)d_in[3];   // [O]
    float* out = (float*)d_out;                   // [B, O, N]

    k_xx<<<(Bc * Nc) / 256, 256>>>(x);
    k_prep<<<16, 256>>>(W);
    k_pq<<<dim3(Nc / 32, Bc), 256>>>(x);
    k_knn<<<dim3(Nc / 64, Bc), 64>>>(x);
    k_edge<<<512, 256>>>();
    k_fin<<<1, Oc>>>(gamma, beta);
    k_out<<<dim3(Nc / 64, Bc), 256>>>(out);
}

// round 2
// speedup vs baseline: 1.8801x; 1.8801x over previous
#include <cuda_runtime.h>
#include <math.h>

// Problem constants
constexpr int Bc = 8;
constexpr int Cc = 64;
constexpr int Nc = 4096;
constexpr int Kc = 20;
constexpr int Oc = 64;
constexpr float BN_EPS = 1e-5f;
constexpr float NEG_SLOPE = 0.2f;
constexpr float FLT_BIG = 3.4e38f;

constexpr int SPLIT = 4;          // j-dimension splits for the KNN kernel
constexpr int JR = Nc / SPLIT;    // 1024 candidates per split
constexpr int TJ2 = 32;           // j tile per iteration

// -------------------- device scratch (no allocations allowed) --------------------
__device__ float  g_xx[Bc * Nc];                  // squared norms
__device__ int    g_idx[Bc * Nc * Kc];            // final knn indices
__device__ float  g_pd[Bc * SPLIT * Nc * Kc];     // partial top-k dists
__device__ int    g_pi[Bc * SPLIT * Nc * Kc];     // partial top-k indices
__device__ float  g_P[Bc * Nc * Oc];              // W1 . x_j   projection
__device__ float  g_Q[Bc * Nc * Oc];              // (W2-W1) . x_i projection
__device__ float  g_mx[Bc * Nc * Oc];             // max_k h
__device__ float  g_mn[Bc * Nc * Oc];             // min_k h
__device__ double g_sum[Oc];
__device__ double g_sumsq[Oc];
__device__ float  g_scale[Oc];
__device__ float  g_shift[Oc];
__device__ float  g_W1t[Cc * Oc];                 // W[:, :C] transposed [c][o]
__device__ float  g_Wdt[Cc * Oc];                 // W[:, C:] - W[:, :C] transposed [c][o]

// -------------------- f32x2 packed helpers (sm_103a FFMA2 path) --------------------
__device__ __forceinline__ unsigned long long pack2(float lo, float hi) {
    unsigned long long r;
    asm("mov.b64 %0, {%1, %2};" : "=l"(r) : "f"(lo), "f"(hi));
    return r;
}
__device__ __forceinline__ void unpack2(unsigned long long v, float& lo, float& hi) {
    asm("mov.b64 {%0, %1}, %2;" : "=f"(lo), "=f"(hi) : "l"(v));
}
__device__ __forceinline__ void ffma2(unsigned long long& d,
                                      unsigned long long a, unsigned long long b) {
    asm("fma.rn.f32x2 %0, %1, %2, %0;" : "+l"(d) : "l"(a), "l"(b));
}

// -------------------- kernel: squared norms --------------------
__global__ void k_xx(const float* __restrict__ x) {
    int t = blockIdx.x * blockDim.x + threadIdx.x;    // over B*N
    int b = t >> 12;
    int n = t & (Nc - 1);
    const float* xb = x + (size_t)b * Cc * Nc + n;
    float s = 0.f;
#pragma unroll
    for (int c = 0; c < Cc; ++c) {
        float v = xb[c * Nc];
        s = fmaf(v, v, s);
    }
    g_xx[t] = s;
}

// -------------------- kernel: prep W transposes + zero stats --------------------
__global__ void k_prep(const float* __restrict__ W) {
    int t = blockIdx.x * blockDim.x + threadIdx.x;
    if (t < Cc * Oc) {
        int c = t & 63;
        int o = t >> 6;
        float w1 = W[o * (2 * Cc) + c];
        float w2 = W[o * (2 * Cc) + Cc + c];
        g_W1t[c * Oc + o] = w1;
        g_Wdt[c * Oc + o] = w2 - w1;
    }
    if (blockIdx.x == 0 && t < Oc) {
        g_sum[t] = 0.0;
        g_sumsq[t] = 0.0;
    }
}

// -------------------- kernel: P and Q projections --------------------
__global__ void __launch_bounds__(256) k_pq(const float* __restrict__ x) {
    int b  = blockIdx.y;
    int n0 = blockIdx.x * 32;
    int o  = threadIdx.x & 63;
    int gg = threadIdx.x >> 6;
    __shared__ float xs[Cc][36];

    for (int t = threadIdx.x; t < Cc * 32; t += 256) {
        int nn = t & 31;
        int c  = t >> 5;
        xs[c][nn] = x[(size_t)b * Cc * Nc + c * Nc + n0 + nn];
    }
    __syncthreads();

    float ap[8], aq[8];
#pragma unroll
    for (int r = 0; r < 8; ++r) { ap[r] = 0.f; aq[r] = 0.f; }
    const int nbase = gg * 8;

#pragma unroll 8
    for (int c = 0; c < Cc; ++c) {
        float w1 = __ldg(&g_W1t[c * Oc + o]);
        float wd = __ldg(&g_Wdt[c * Oc + o]);
        float4 v0 = *(const float4*)&xs[c][nbase];
        float4 v1 = *(const float4*)&xs[c][nbase + 4];
        ap[0] = fmaf(w1, v0.x, ap[0]); aq[0] = fmaf(wd, v0.x, aq[0]);
        ap[1] = fmaf(w1, v0.y, ap[1]); aq[1] = fmaf(wd, v0.y, aq[1]);
        ap[2] = fmaf(w1, v0.z, ap[2]); aq[2] = fmaf(wd, v0.z, aq[2]);
        ap[3] = fmaf(w1, v0.w, ap[3]); aq[3] = fmaf(wd, v0.w, aq[3]);
        ap[4] = fmaf(w1, v1.x, ap[4]); aq[4] = fmaf(wd, v1.x, aq[4]);
        ap[5] = fmaf(w1, v1.y, ap[5]); aq[5] = fmaf(wd, v1.y, aq[5]);
        ap[6] = fmaf(w1, v1.z, ap[6]); aq[6] = fmaf(wd, v1.z, aq[6]);
        ap[7] = fmaf(w1, v1.w, ap[7]); aq[7] = fmaf(wd, v1.w, aq[7]);
    }

    int row0 = b * Nc + n0 + nbase;
#pragma unroll
    for (int r = 0; r < 8; ++r) {
        g_P[(size_t)(row0 + r) * Oc + o] = ap[r];
        g_Q[(size_t)(row0 + r) * Oc + o] = aq[r];
    }
}

// -------------------- kernel: KNN over a j-split, f32x2 math, shared top-k --------------------
// grid = (N/64, B, SPLIT), block = 64. Thread t owns query i = blockIdx.x*64+t,
// scans j in [s*JR, (s+1)*JR), keeps top-K in shared (per-thread column).
__global__ void __launch_bounds__(64) k_knn2(const float* __restrict__ x) {
    int b   = blockIdx.y;
    int s   = blockIdx.z;
    int tid = threadIdx.x;
    int i   = blockIdx.x * 64 + tid;
    const float* xb = x + (size_t)b * Cc * Nc;

    // query packed as f32x2 pairs, pre-scaled by -2 (folds the -2*inner term)
    unsigned long long q2[32];
#pragma unroll
    for (int cp = 0; cp < 32; ++cp) {
        float a  = xb[(2 * cp) * Nc + i] * -2.f;
        float bq = xb[(2 * cp + 1) * Nc + i] * -2.f;
        q2[cp] = pack2(a, bq);
    }
    float xxi = g_xx[b * Nc + i];

    __shared__ unsigned long long s2[TJ2][34];  // point tile, packed channel pairs
    __shared__ float sxx[TJ2];
    __shared__ float sd[Kc][64];                // per-thread top-k dists
    __shared__ int   si[Kc][64];                // per-thread top-k indices
#pragma unroll
    for (int kk = 0; kk < Kc; ++kk) { sd[kk][tid] = FLT_BIG; si[kk][tid] = -1; }
    float worst = FLT_BIG;

    const int j0beg = s * JR;
    for (int j0 = j0beg; j0 < j0beg + JR; j0 += TJ2) {
        __syncthreads();
#pragma unroll
        for (int t = tid; t < TJ2 * 32; t += 64) {
            int jj = t & (TJ2 - 1);
            int cp = t >> 5;
            float a  = xb[(2 * cp) * Nc + j0 + jj];
            float bq = xb[(2 * cp + 1) * Nc + j0 + jj];
            s2[jj][cp] = pack2(a, bq);
        }
        if (tid < TJ2) sxx[tid] = g_xx[b * Nc + j0 + tid];
        __syncthreads();

#pragma unroll 1
        for (int jj = 0; jj < TJ2; jj += 8) {
            unsigned long long acc[8];
#pragma unroll
            for (int r = 0; r < 8; ++r) acc[r] = 0ULL;

#pragma unroll
            for (int cp = 0; cp < 32; cp += 2) {
#pragma unroll
                for (int r = 0; r < 8; ++r) {
                    ulonglong2 v = *(const ulonglong2*)&s2[jj + r][cp];
                    ffma2(acc[r], q2[cp], v.x);
                    ffma2(acc[r], q2[cp + 1], v.y);
                }
            }

#pragma unroll
            for (int r = 0; r < 8; ++r) {
                float lo, hi;
                unpack2(acc[r], lo, hi);
                float d = xxi + sxx[jj + r] + (lo + hi);
                if (d < worst) {
                    int jidx = j0 + jj + r;
                    int p = Kc - 1;
                    while (p > 0) {
                        float v = sd[p - 1][tid];
                        if (!(v > d)) break;
                        sd[p][tid] = v;
                        si[p][tid] = si[p - 1][tid];
                        --p;
                    }
                    sd[p][tid] = d;
                    si[p][tid] = jidx;
                    worst = sd[Kc - 1][tid];
                }
            }
        }
    }

    size_t base = (((size_t)b * SPLIT + s) * Nc + i) * Kc;
#pragma unroll
    for (int kk = 0; kk < Kc; ++kk) {
        g_pd[base + kk] = sd[kk][tid];
        g_pi[base + kk] = si[kk][tid];
    }
}

// -------------------- kernel: merge SPLIT sorted partial top-k lists --------------------
__global__ void __launch_bounds__(256) k_merge() {
    int t = blockIdx.x * blockDim.x + threadIdx.x;   // over B*N
    int b = t >> 12;
    int i = t & (Nc - 1);
    float td[Kc];
    int   ti[Kc];
#pragma unroll
    for (int kk = 0; kk < Kc; ++kk) { td[kk] = FLT_BIG; ti[kk] = -1; }
    float worst = FLT_BIG;

    for (int s = 0; s < SPLIT; ++s) {
        size_t base = (((size_t)b * SPLIT + s) * Nc + i) * Kc;
#pragma unroll 1
        for (int kk = 0; kk < Kc; ++kk) {
            float d = g_pd[base + kk];
            if (!(d < worst)) break;   // lists sorted ascending; rest can't qualify
            int j = g_pi[base + kk];
            int p = Kc - 1;
            while (p > 0 && td[p - 1] > d) {
                td[p] = td[p - 1];
                ti[p] = ti[p - 1];
                --p;
            }
            td[p] = d;
            ti[p] = j;
            worst = td[Kc - 1];
        }
    }

    int* op = &g_idx[(size_t)t * Kc];
#pragma unroll
    for (int kk = 0; kk < Kc; ++kk) op[kk] = ti[kk];
}

// -------------------- kernel: gather + max/min + BN stats --------------------
__global__ void __launch_bounds__(256) k_edge() {
    int o  = threadIdx.x & 63;
    int gg = threadIdx.x >> 6;
    float s1 = 0.f, s2v = 0.f;

    for (int row = blockIdx.x * 4 + gg; row < Bc * Nc; row += gridDim.x * 4) {
        int b  = row >> 12;
        int nb = b << 12;
        float qv = g_Q[(size_t)row * Oc + o];
        const int* ip = &g_idx[(size_t)row * Kc];
        float mx = -FLT_BIG, mn = FLT_BIG;
#pragma unroll
        for (int kk = 0; kk < Kc; ++kk) {
            int j = __ldg(&ip[kk]);
            float h = g_P[(size_t)(nb + j) * Oc + o] + qv;
            mx = fmaxf(mx, h);
            mn = fminf(mn, h);
            s1 += h;
            s2v = fmaf(h, h, s2v);
        }
        g_mx[(size_t)row * Oc + o] = mx;
        g_mn[(size_t)row * Oc + o] = mn;
    }

    __shared__ float sa[4][64], sb[4][64];
    sa[gg][o] = s1;
    sb[gg][o] = s2v;
    __syncthreads();
    if (gg == 0) {
        float t1 = sa[0][o] + sa[1][o] + sa[2][o] + sa[3][o];
        float t2 = sb[0][o] + sb[1][o] + sb[2][o] + sb[3][o];
        atomicAdd(&g_sum[o], (double)t1);
        atomicAdd(&g_sumsq[o], (double)t2);
    }
}

// -------------------- kernel: finalize BN affine --------------------
__global__ void k_fin(const float* __restrict__ gamma, const float* __restrict__ beta) {
    int o = threadIdx.x;
    const double cnt = (double)Bc * Nc * Kc;
    double mean = g_sum[o] / cnt;
    double var  = g_sumsq[o] / cnt - mean * mean;
    float a = gamma[o] * rsqrtf((float)var + BN_EPS);
    g_scale[o] = a;
    g_shift[o] = beta[o] - (float)mean * a;
}

// -------------------- kernel: apply affine + leaky + transpose to [B,O,N] --------------------
__global__ void __launch_bounds__(256) k_out(float* __restrict__ out) {
    int b  = blockIdx.y;
    int n0 = blockIdx.x * 64;
    __shared__ float sh[64][65];

    for (int t = threadIdx.x; t < 4096; t += 256) {
        int o  = t & 63;
        int nn = t >> 6;
        int row = b * Nc + n0 + nn;
        float a = g_scale[o];
        float m = (a >= 0.f) ? g_mx[(size_t)row * Oc + o] : g_mn[(size_t)row * Oc + o];
        float v = fmaf(a, m, g_shift[o]);
        v = (v >= 0.f) ? v : NEG_SLOPE * v;
        sh[o][nn] = v;
    }
    __syncthreads();
    for (int t = threadIdx.x; t < 4096; t += 256) {
        int nn = t & 63;
        int o  = t >> 6;
        out[((size_t)(b * Oc + o)) * Nc + n0 + nn] = sh[o][nn];
    }
}

// -------------------- launch --------------------
extern "C" void kernel_launch(void* const* d_in, const int* in_sizes, int n_in,
                              void* d_out, int out_size) {
    const float* x     = (const float*)d_in[0];   // [B, C, N]
    const float* W     = (const float*)d_in[1];   // [O, 2C]
    const float* gamma = (const float*)d_in[2];   // [O]
    const float* beta  = (const float*)d_in[3];   // [O]
    float* out = (float*)d_out;                   // [B, O, N]

    k_xx<<<(Bc * Nc) / 256, 256>>>(x);
    k_prep<<<16, 256>>>(W);
    k_pq<<<dim3(Nc / 32, Bc), 256>>>(x);
    k_knn2<<<dim3(Nc / 64, Bc, SPLIT), 64>>>(x);
    k_merge<<<(Bc * Nc) / 256, 256>>>();
    k_edge<<<512, 256>>>();
    k_fin<<<1, Oc>>>(gamma, beta);
    k_out<<<dim3(Nc / 64, Bc), 256>>>(out);
}